// round 14
// baseline (speedup 1.0000x reference)
#include <cuda_runtime.h>
#include <cstdint>

// Problem constants (fixed by the dataset shapes)
#define DIMS 1024            // embedding dim, fp32
#define V4_PER_ROW 256       // 1024 / 4
#define PAIRS_PER_CTA 4      // 64 threads (2 warps) per pair
#define CTA_THREADS 256
#define VOCAB 50257
#define N_SLOTS 16

#define EPS 1e-8f
#define WEIGHT 0.01f

#define FIX_BITS 34
#define SUM_MASK ((1ULL << 48) - 1ULL)
#define CNT_ONE  (1ULL << 48)

// Two-level packed accumulators. Each u64: bits[0,48) fixed-point loss sum,
// bits[48,64) completion count. All atomics are RELAXED integer adds ->
// deterministic, no fences. Winners atomicExch back to 0 -> graph-replay safe.
// Slots strided 16*8=128B apart so they land on distinct L2 slices (parallel
// atomic ALUs instead of one serialized address).
__device__ unsigned long long g_slots[N_SLOTS * 16];
__device__ unsigned long long g_master;

__global__ __launch_bounds__(CTA_THREADS) void anchor_loss_kernel(
    const float* __restrict__ W,
    const int* __restrict__ archaic_idx,
    const int* __restrict__ modern_idx,
    float* __restrict__ out,
    int n_pairs, int n_ctas)
{
    const int t     = threadIdx.x;
    const int warp  = t >> 5;
    const int lane  = t & 31;
    const int group = t >> 6;            // 0..3, one pair per 64 threads
    const int u     = t & 63;            // lane within group
    const int p     = blockIdx.x * PAIRS_PER_CTA + group;

    float dot = 0.0f, na = 0.0f, nm = 0.0f;

    if (p < n_pairs) {
        int ia = __ldg(archaic_idx + p);
        int im = __ldg(modern_idx + p);
        ia = min(max(ia, 0), VOCAB - 1);
        im = min(max(im, 0), VOCAB - 1);

        const float4* __restrict__ a4 =
            reinterpret_cast<const float4*>(W + (size_t)ia * DIMS) + u;
        const float4* __restrict__ m4 =
            reinterpret_cast<const float4*>(W + (size_t)im * DIMS) + u;

        // 8 independent LDG.128 in flight per thread (4 per row).
        float4 av[4], mv[4];
        #pragma unroll
        for (int i = 0; i < 4; i++) av[i] = a4[i * 64];
        #pragma unroll
        for (int i = 0; i < 4; i++) mv[i] = m4[i * 64];

        #pragma unroll
        for (int i = 0; i < 4; i++) {
            dot = fmaf(av[i].x, mv[i].x, fmaf(av[i].y, mv[i].y,
                  fmaf(av[i].z, mv[i].z, fmaf(av[i].w, mv[i].w, dot))));
            na  = fmaf(av[i].x, av[i].x, fmaf(av[i].y, av[i].y,
                  fmaf(av[i].z, av[i].z, fmaf(av[i].w, av[i].w, na))));
            nm  = fmaf(mv[i].x, mv[i].x, fmaf(mv[i].y, mv[i].y,
                  fmaf(mv[i].z, mv[i].z, fmaf(mv[i].w, mv[i].w, nm))));
        }
    }

    // Per-warp shuffle reduce
    #pragma unroll
    for (int off = 16; off > 0; off >>= 1) {
        dot += __shfl_down_sync(0xFFFFFFFFu, dot, off);
        na  += __shfl_down_sync(0xFFFFFFFFu, na,  off);
        nm  += __shfl_down_sync(0xFFFFFFFFu, nm,  off);
    }

    __shared__ float s_dot[8], s_na[8], s_nm[8];
    if (lane == 0) {
        s_dot[warp] = dot;
        s_na[warp]  = na;
        s_nm[warp]  = nm;
    }
    __syncthreads();

    // Warp 0, lanes 0..3: combine the two warps of pair g, compute its loss,
    // sum the 4 losses, quantize, feed the two-level atomic tree.
    if (warp == 0) {
        float loss = 0.0f;
        if (lane < PAIRS_PER_CTA) {
            const int pg = blockIdx.x * PAIRS_PER_CTA + lane;
            if (pg < n_pairs) {
                const float d = s_dot[2 * lane] + s_dot[2 * lane + 1];
                const float a = s_na[2 * lane]  + s_na[2 * lane + 1];
                const float m = s_nm[2 * lane]  + s_nm[2 * lane + 1];
                const float den = fmaxf(sqrtf(a), EPS) * fmaxf(sqrtf(m), EPS);
                loss = fmaxf(1.0f - d / den, 0.0f);
            }
        }
        loss += __shfl_down_sync(0xFFFFFFFFu, loss, 2);
        loss += __shfl_down_sync(0xFFFFFFFFu, loss, 1);

        if (lane == 0) {
            const unsigned long long q =
                (unsigned long long)llrintf(loss * (float)(1ULL << FIX_BITS));

            const int s = blockIdx.x & (N_SLOTS - 1);
            // CTAs mapped to slot s: count of b in [0,n_ctas) with b%16==s.
            const int quota = (n_ctas - 1 - s) / N_SLOTS + 1;

            unsigned long long* slot = &g_slots[s * 16];
            const unsigned long long old = atomicAdd(slot, CNT_ONE | q);

            if ((old >> 48) == (unsigned long long)(quota - 1)) {
                // Slot complete: drain it (and reset), escalate to master.
                const unsigned long long tot = atomicExch(slot, 0ULL);
                const int n_slots_used = (n_ctas < N_SLOTS) ? n_ctas : N_SLOTS;
                const unsigned long long mold =
                    atomicAdd(&g_master, CNT_ONE | (tot & SUM_MASK));
                if ((mold >> 48) == (unsigned long long)(n_slots_used - 1)) {
                    const unsigned long long mtot = atomicExch(&g_master, 0ULL);
                    const double sum = (double)(mtot & SUM_MASK) *
                                       (1.0 / (double)(1ULL << FIX_BITS));
                    out[0] = (float)((double)WEIGHT * sum / (double)n_pairs);
                }
            }
        }
    }
}

extern "C" void kernel_launch(void* const* d_in, const int* in_sizes, int n_in,
                              void* d_out, int out_size)
{
    const float* W  = (const float*)d_in[0];   // [50257, 1024] fp32
    const int*   ai = (const int*)d_in[1];     // [n_pairs] int32
    const int*   mi = (const int*)d_in[2];     // [n_pairs] int32
    float* out = (float*)d_out;

    int n_pairs = in_sizes[1];
    if (n_pairs < 1) n_pairs = 1;

    const int n_ctas = (n_pairs + PAIRS_PER_CTA - 1) / PAIRS_PER_CTA;  // 1024

    anchor_loss_kernel<<<n_ctas, CTA_THREADS>>>(W, ai, mi, out, n_pairs, n_ctas);
}

// round 16
// speedup vs baseline: 2.2509x; 2.2509x over previous
#include <cuda_runtime.h>
#include <cstdint>

// Problem constants (fixed by the dataset shapes)
#define DIMS 1024            // embedding dim, fp32
#define PAIRS_PER_CTA 8      // one pair per warp
#define CTA_THREADS 256
#define VOCAB 50257

#define EPS 1e-8f
#define WEIGHT 0.01f

#define FIX_BITS 34
#define SUM_MASK ((1ULL << 48) - 1ULL)
#define CNT_ONE  (1ULL << 48)

// Single packed accumulator: bits[0,48) fixed-point sum of (1-sim),
// bits[48,64) CTA completion count. One RELAXED u64 atomicAdd per CTA carries
// data + ticket: no fences, no MEMBAR, no L1 flush, deterministic (integer
// adds commute). Winner atomicExch's it to 0 -> graph-replay safe.
__device__ unsigned long long g_acc = 0ULL;

__global__ __launch_bounds__(CTA_THREADS) void anchor_loss_kernel(
    const float* __restrict__ W,
    const int* __restrict__ archaic_idx,
    const int* __restrict__ modern_idx,
    float* __restrict__ out,
    int n_pairs, int n_ctas)
{
    const int warp = threadIdx.x >> 5;
    const int lane = threadIdx.x & 31;
    const int p    = blockIdx.x * PAIRS_PER_CTA + warp;

    __shared__ float s_loss[PAIRS_PER_CTA];

    float dot = 0.0f, na = 0.0f, nm = 0.0f;

    if (p < n_pairs) {
        int ia = __ldg(archaic_idx + p);
        int im = __ldg(modern_idx + p);
        ia = min(max(ia, 0), VOCAB - 1);
        im = min(max(im, 0), VOCAB - 1);

        const float4* __restrict__ a4 =
            reinterpret_cast<const float4*>(W + (size_t)ia * DIMS) + lane;
        const float4* __restrict__ m4 =
            reinterpret_cast<const float4*>(W + (size_t)im * DIMS) + lane;

        // Two chunks of (4 a-loads + 4 m-loads), FMA between chunks — exactly
        // the R9 memory pattern (best measured bench config).
        #pragma unroll
        for (int c = 0; c < 2; c++) {
            float4 av[4], mv[4];
            #pragma unroll
            for (int i = 0; i < 4; i++) av[i] = a4[(c * 4 + i) * 32];
            #pragma unroll
            for (int i = 0; i < 4; i++) mv[i] = m4[(c * 4 + i) * 32];
            #pragma unroll
            for (int i = 0; i < 4; i++) {
                dot = fmaf(av[i].x, mv[i].x, fmaf(av[i].y, mv[i].y,
                      fmaf(av[i].z, mv[i].z, fmaf(av[i].w, mv[i].w, dot))));
                na  = fmaf(av[i].x, av[i].x, fmaf(av[i].y, av[i].y,
                      fmaf(av[i].z, av[i].z, fmaf(av[i].w, av[i].w, na))));
                nm  = fmaf(mv[i].x, mv[i].x, fmaf(mv[i].y, mv[i].y,
                      fmaf(mv[i].z, mv[i].z, fmaf(mv[i].w, mv[i].w, nm))));
            }
        }
    }

    // Warp-level reduce (3 values, 5 rounds)
    #pragma unroll
    for (int off = 16; off > 0; off >>= 1) {
        dot += __shfl_down_sync(0xFFFFFFFFu, dot, off);
        na  += __shfl_down_sync(0xFFFFFFFFu, na,  off);
        nm  += __shfl_down_sync(0xFFFFFFFFu, nm,  off);
    }

    if (lane == 0) {
        if (p < n_pairs) {
            const float den = fmaxf(sqrtf(na), EPS) * fmaxf(sqrtf(nm), EPS);
            s_loss[warp] = fmaxf(1.0f - dot / den, 0.0f);
        } else {
            s_loss[warp] = 0.0f;
        }
    }
    __syncthreads();

    // Warp 0: sum the 8 per-pair losses, quantize, single relaxed atomic.
    if (warp == 0) {
        float c = (lane < PAIRS_PER_CTA) ? s_loss[lane] : 0.0f;
        #pragma unroll
        for (int off = 4; off > 0; off >>= 1)
            c += __shfl_down_sync(0xFFFFFFFFu, c, off);

        if (lane == 0) {
            const unsigned long long q =
                (unsigned long long)llrintf(c * (float)(1ULL << FIX_BITS));

            const unsigned long long old = atomicAdd(&g_acc, CNT_ONE | q);

            if ((old >> 48) == (unsigned long long)(n_ctas - 1)) {
                // Last CTA: read complete total and reset for the next replay.
                const unsigned long long tot = atomicExch(&g_acc, 0ULL);
                const double sum =
                    (double)(tot & SUM_MASK) * (1.0 / (double)(1ULL << FIX_BITS));
                out[0] = (float)((double)WEIGHT * sum / (double)n_pairs);
            }
        }
    }
}

extern "C" void kernel_launch(void* const* d_in, const int* in_sizes, int n_in,
                              void* d_out, int out_size)
{
    const float* W  = (const float*)d_in[0];   // [50257, 1024] fp32
    const int*   ai = (const int*)d_in[1];     // [n_pairs] int32
    const int*   mi = (const int*)d_in[2];     // [n_pairs] int32
    float* out = (float*)d_out;

    int n_pairs = in_sizes[1];
    if (n_pairs < 1) n_pairs = 1;

    const int n_ctas = (n_pairs + PAIRS_PER_CTA - 1) / PAIRS_PER_CTA;  // 512

    anchor_loss_kernel<<<n_ctas, CTA_THREADS>>>(W, ai, mi, out, n_pairs, n_ctas);
}